// round 8
// baseline (speedup 1.0000x reference)
#include <cuda_runtime.h>
#include <math.h>

#define BB 32
#define SS 1024
#define NTOK (BB*SS)      // 32768 tokens
#define HH 32
#define WW 32
#define HWB (HH*WW)       // 1024 bins
#define P2 256
#define CC 3
#define DD (CC*P2)        // 768
#define MAXB 192
#define SPLIT 4           // stats sub-blocks per bin
#define EPSV 1e-6f

// ---- scratch (device globals; no allocation) ----
__device__ int   g_bincount[HWB];
__device__ int   g_binlist[HWB * MAXB];            // 768 KB
__device__ float g_ps1[SPLIT * HWB * P2];          // 4 MB partial S1
__device__ float g_ps2[SPLIT * HWB * P2];          // 4 MB partial S2
__device__ float g_mnew[HWB * P2];                 // mean_new  (1 MB)
__device__ float g_rstd[HWB * P2];                 // 1/(std+eps)

// ---------------------------------------------------------------------------
// K0: zero bin counters (graph replays -> must reset every launch)
// ---------------------------------------------------------------------------
__global__ void k_zero() {
    int i = blockIdx.x * blockDim.x + threadIdx.x;
    if (i < HWB) g_bincount[i] = 0;
}

// ---------------------------------------------------------------------------
// K1: bin valid tokens by flat grid index pf (mask is int32; nonzero = pad)
// ---------------------------------------------------------------------------
__global__ void k_bin(const int* __restrict__ pos_h,
                      const int* __restrict__ pos_w,
                      const int* __restrict__ mask) {
    int t = blockIdx.x * blockDim.x + threadIdx.x;
    if (t >= NTOK) return;
    if (mask[t] != 0) return;
    int pf = pos_h[t] * WW + pos_w[t];
    int idx = atomicAdd(&g_bincount[pf], 1);
    if (idx < MAXB) g_binlist[pf * MAXB + idx] = t;
}

// ---------------------------------------------------------------------------
// K2a: partial Welford sums. grid = (HWB, SPLIT); block part handles tokens
//      j = part, part+SPLIT, ... of its bin. a_i = xbar_i - mean_old;
//      partial S1 = sum a, S2 = sum a^2 written to a private slot (no atomics).
// ---------------------------------------------------------------------------
__global__ void __launch_bounds__(P2) k_stats_part(const float* __restrict__ patches,
                                                   const float* __restrict__ mean_in) {
    int bin  = blockIdx.x;
    int part = blockIdx.y;
    int p = threadIdx.x;                         // 0..255

    __shared__ int s_tok[MAXB];
    __shared__ int s_cnt;
    if (p == 0) s_cnt = min(g_bincount[bin], MAXB);
    __syncthreads();
    int cnt = s_cnt;
    for (int i = p; i < cnt; i += P2) s_tok[i] = g_binlist[bin * MAXB + i];
    __syncthreads();

    float mo = mean_in[(size_t)bin * P2 + p];
    float s1 = 0.f, s2 = 0.f;
    const float c3 = 1.0f / 3.0f;

    int i = part;
    for (; i + 3 * SPLIT < cnt; i += 4 * SPLIT) {   // 4 tokens -> 12 loads in flight
        const float* b0 = patches + (size_t)s_tok[i]             * DD;
        const float* b1 = patches + (size_t)s_tok[i +     SPLIT] * DD;
        const float* b2 = patches + (size_t)s_tok[i + 2 * SPLIT] * DD;
        const float* b3 = patches + (size_t)s_tok[i + 3 * SPLIT] * DD;
        float x00 = b0[p], x01 = b0[p + 256], x02 = b0[p + 512];
        float x10 = b1[p], x11 = b1[p + 256], x12 = b1[p + 512];
        float x20 = b2[p], x21 = b2[p + 256], x22 = b2[p + 512];
        float x30 = b3[p], x31 = b3[p + 256], x32 = b3[p + 512];
        float a0 = (x00 + x01 + x02) * c3 - mo;
        float a1 = (x10 + x11 + x12) * c3 - mo;
        float a2 = (x20 + x21 + x22) * c3 - mo;
        float a3 = (x30 + x31 + x32) * c3 - mo;
        s1 += a0; s2 += a0 * a0;
        s1 += a1; s2 += a1 * a1;
        s1 += a2; s2 += a2 * a2;
        s1 += a3; s2 += a3 * a3;
    }
    for (; i < cnt; i += SPLIT) {
        const float* b0 = patches + (size_t)s_tok[i] * DD;
        float a0 = (b0[p] + b0[p + 256] + b0[p + 512]) * c3 - mo;
        s1 += a0; s2 += a0 * a0;
    }

    size_t slot = ((size_t)part * HWB + bin) * P2 + p;
    g_ps1[slot] = s1;
    g_ps2[slot] = s2;
}

// ---------------------------------------------------------------------------
// K2b: finalize per (bin,p): combine SPLIT partials, compute mean_new + rstd.
//      float4 over HWB*P2/4 elements; partials are L2-resident.
// ---------------------------------------------------------------------------
__global__ void k_finalize(const float* __restrict__ n_in,
                           const float* __restrict__ mean_in,
                           const float* __restrict__ m2_in) {
    int i = blockIdx.x * blockDim.x + threadIdx.x;   // float4 index, HWB*P2/4
    if (i >= HWB * P2 / 4) return;
    int bin = i / (P2 / 4);

    float4 s1 = make_float4(0.f, 0.f, 0.f, 0.f);
    float4 s2 = make_float4(0.f, 0.f, 0.f, 0.f);
#pragma unroll
    for (int part = 0; part < SPLIT; part++) {
        float4 a = ((const float4*)g_ps1)[(size_t)part * (HWB * P2 / 4) + i];
        float4 b = ((const float4*)g_ps2)[(size_t)part * (HWB * P2 / 4) + i];
        s1.x += a.x; s1.y += a.y; s1.z += a.z; s1.w += a.w;
        s2.x += b.x; s2.y += b.y; s2.z += b.z; s2.w += b.w;
    }

    float nn = n_in[bin] + (float)min(g_bincount[bin], MAXB);
    float ng = fmaxf(nn, 1.0f);
    float inv = 1.0f / ng;
    bool small = (nn < 2.0f);

    float4 mo = ((const float4*)mean_in)[i];
    float4 m2 = ((const float4*)m2_in)[i];
    float4 mn, rs;
    float u, m2v, var;

    u = s1.x * inv; mn.x = mo.x + u; m2v = m2.x + (s2.x - u * s1.x);
    var = small ? 1.0f : m2v * inv; rs.x = 1.0f / (sqrtf(var) + EPSV);
    u = s1.y * inv; mn.y = mo.y + u; m2v = m2.y + (s2.y - u * s1.y);
    var = small ? 1.0f : m2v * inv; rs.y = 1.0f / (sqrtf(var) + EPSV);
    u = s1.z * inv; mn.z = mo.z + u; m2v = m2.z + (s2.z - u * s1.z);
    var = small ? 1.0f : m2v * inv; rs.z = 1.0f / (sqrtf(var) + EPSV);
    u = s1.w * inv; mn.w = mo.w + u; m2v = m2.w + (s2.w - u * s1.w);
    var = small ? 1.0f : m2v * inv; rs.w = 1.0f / (sqrtf(var) + EPSV);

    ((float4*)g_mnew)[i] = mn;
    ((float4*)g_rstd)[i] = rs;
}

// ---------------------------------------------------------------------------
// K3: normalize. 64 lanes handle TWO tokens (10 loads in flight, stat gathers
//     deduped across channels). Block = 256 threads = 8 tokens.
// ---------------------------------------------------------------------------
__global__ void __launch_bounds__(256) k_norm(const float* __restrict__ patches,
                                              const int* __restrict__ pos_h,
                                              const int* __restrict__ pos_w,
                                              const int* __restrict__ mask,
                                              float* __restrict__ out) {
    int g = blockIdx.x * 4 + (threadIdx.x >> 6);     // token-pair index
    int lane = threadIdx.x & 63;
    int t0 = g * 2, t1 = t0 + 1;

    const float4* xr0 = (const float4*)(patches + (size_t)t0 * DD);
    const float4* xr1 = (const float4*)(patches + (size_t)t1 * DD);
    float4* or0 = (float4*)(out + (size_t)t0 * DD);
    float4* or1 = (float4*)(out + (size_t)t1 * DD);

    int m0 = mask[t0], m1 = mask[t1];
    float4 z = make_float4(0.f, 0.f, 0.f, 0.f);

    if ((m0 | m1) == 0) {                            // fast path: both valid
        int pf0 = pos_h[t0] * WW + pos_w[t0];
        int pf1 = pos_h[t1] * WW + pos_w[t1];
        float4 x00 = xr0[lane], x01 = xr0[lane + 64], x02 = xr0[lane + 128];
        float4 x10 = xr1[lane], x11 = xr1[lane + 64], x12 = xr1[lane + 128];
        float4 mn0 = ((const float4*)(g_mnew + (size_t)pf0 * P2))[lane];
        float4 rs0 = ((const float4*)(g_rstd + (size_t)pf0 * P2))[lane];
        float4 mn1 = ((const float4*)(g_mnew + (size_t)pf1 * P2))[lane];
        float4 rs1 = ((const float4*)(g_rstd + (size_t)pf1 * P2))[lane];

        float4 o;
        o.x = (x00.x - mn0.x) * rs0.x; o.y = (x00.y - mn0.y) * rs0.y;
        o.z = (x00.z - mn0.z) * rs0.z; o.w = (x00.w - mn0.w) * rs0.w;
        or0[lane] = o;
        o.x = (x01.x - mn0.x) * rs0.x; o.y = (x01.y - mn0.y) * rs0.y;
        o.z = (x01.z - mn0.z) * rs0.z; o.w = (x01.w - mn0.w) * rs0.w;
        or0[lane + 64] = o;
        o.x = (x02.x - mn0.x) * rs0.x; o.y = (x02.y - mn0.y) * rs0.y;
        o.z = (x02.z - mn0.z) * rs0.z; o.w = (x02.w - mn0.w) * rs0.w;
        or0[lane + 128] = o;
        o.x = (x10.x - mn1.x) * rs1.x; o.y = (x10.y - mn1.y) * rs1.y;
        o.z = (x10.z - mn1.z) * rs1.z; o.w = (x10.w - mn1.w) * rs1.w;
        or1[lane] = o;
        o.x = (x11.x - mn1.x) * rs1.x; o.y = (x11.y - mn1.y) * rs1.y;
        o.z = (x11.z - mn1.z) * rs1.z; o.w = (x11.w - mn1.w) * rs1.w;
        or1[lane + 64] = o;
        o.x = (x12.x - mn1.x) * rs1.x; o.y = (x12.y - mn1.y) * rs1.y;
        o.z = (x12.z - mn1.z) * rs1.z; o.w = (x12.w - mn1.w) * rs1.w;
        or1[lane + 128] = o;
        return;
    }

    // slow path: at least one masked
    if (m0 != 0) {
        or0[lane] = z; or0[lane + 64] = z; or0[lane + 128] = z;
    } else {
        int pf0 = pos_h[t0] * WW + pos_w[t0];
        float4 x00 = xr0[lane], x01 = xr0[lane + 64], x02 = xr0[lane + 128];
        float4 mn0 = ((const float4*)(g_mnew + (size_t)pf0 * P2))[lane];
        float4 rs0 = ((const float4*)(g_rstd + (size_t)pf0 * P2))[lane];
        float4 o;
        o.x = (x00.x - mn0.x) * rs0.x; o.y = (x00.y - mn0.y) * rs0.y;
        o.z = (x00.z - mn0.z) * rs0.z; o.w = (x00.w - mn0.w) * rs0.w;
        or0[lane] = o;
        o.x = (x01.x - mn0.x) * rs0.x; o.y = (x01.y - mn0.y) * rs0.y;
        o.z = (x01.z - mn0.z) * rs0.z; o.w = (x01.w - mn0.w) * rs0.w;
        or0[lane + 64] = o;
        o.x = (x02.x - mn0.x) * rs0.x; o.y = (x02.y - mn0.y) * rs0.y;
        o.z = (x02.z - mn0.z) * rs0.z; o.w = (x02.w - mn0.w) * rs0.w;
        or0[lane + 128] = o;
    }
    if (m1 != 0) {
        or1[lane] = z; or1[lane + 64] = z; or1[lane + 128] = z;
    } else {
        int pf1 = pos_h[t1] * WW + pos_w[t1];
        float4 x10 = xr1[lane], x11 = xr1[lane + 64], x12 = xr1[lane + 128];
        float4 mn1 = ((const float4*)(g_mnew + (size_t)pf1 * P2))[lane];
        float4 rs1 = ((const float4*)(g_rstd + (size_t)pf1 * P2))[lane];
        float4 o;
        o.x = (x10.x - mn1.x) * rs1.x; o.y = (x10.y - mn1.y) * rs1.y;
        o.z = (x10.z - mn1.z) * rs1.z; o.w = (x10.w - mn1.w) * rs1.w;
        or1[lane] = o;
        o.x = (x11.x - mn1.x) * rs1.x; o.y = (x11.y - mn1.y) * rs1.y;
        o.z = (x11.z - mn1.z) * rs1.z; o.w = (x11.w - mn1.w) * rs1.w;
        or1[lane + 64] = o;
        o.x = (x12.x - mn1.x) * rs1.x; o.y = (x12.y - mn1.y) * rs1.y;
        o.z = (x12.z - mn1.z) * rs1.z; o.w = (x12.w - mn1.w) * rs1.w;
        or1[lane + 128] = o;
    }
}

// ---------------------------------------------------------------------------
extern "C" void kernel_launch(void* const* d_in, const int* in_sizes, int n_in,
                              void* d_out, int out_size) {
    const float* patches = (const float*)d_in[0];
    const int*   pos_h   = (const int*)d_in[1];
    const int*   pos_w   = (const int*)d_in[2];
    const int*   mask    = (const int*)d_in[3];    // bool widened to int32
    const float* n_in0   = (const float*)d_in[4];
    const float* mean_in = (const float*)d_in[5];
    const float* m2_in   = (const float*)d_in[6];
    float*       out     = (float*)d_out;

    k_zero      <<<(HWB + 255) / 256, 256>>>();
    k_bin       <<<(NTOK + 255) / 256, 256>>>(pos_h, pos_w, mask);
    k_stats_part<<<dim3(HWB, SPLIT), P2>>>(patches, mean_in);
    k_finalize  <<<(HWB * P2 / 4 + 255) / 256, 256>>>(n_in0, mean_in, m2_in);
    k_norm      <<<NTOK / 8, 256>>>(patches, pos_h, pos_w, mask, out);
}

// round 9
// speedup vs baseline: 1.1467x; 1.1467x over previous
#include <cuda_runtime.h>
#include <math.h>

#define BB 32
#define SS 1024
#define NTOK (BB*SS)      // 32768 tokens
#define HH 32
#define WW 32
#define HWB (HH*WW)       // 1024 bins
#define P2 256
#define CC 3
#define DD (CC*P2)        // 768
#define MAXB 192
#define EPSV 1e-6f

// ---- scratch (device globals; no allocation) ----
__device__ int   g_bincount[HWB];
__device__ int   g_binlist[HWB * MAXB];   // 768 KB
__device__ float g_mnew[HWB * P2];        // mean_new       (1 MB)
__device__ float g_rstd[HWB * P2];        // 1/(std+eps)    (1 MB)

// ---------------------------------------------------------------------------
// K0: zero bin counters (graph replays -> must reset every launch)
// ---------------------------------------------------------------------------
__global__ void k_zero() {
    int i = blockIdx.x * blockDim.x + threadIdx.x;
    if (i < HWB) g_bincount[i] = 0;
}

// ---------------------------------------------------------------------------
// K1: bin valid tokens by flat grid index pf (mask is int32; nonzero = pad)
// ---------------------------------------------------------------------------
__global__ void k_bin(const int* __restrict__ pos_h,
                      const int* __restrict__ pos_w,
                      const int* __restrict__ mask) {
    int t = blockIdx.x * blockDim.x + threadIdx.x;
    if (t >= NTOK) return;
    if (mask[t] != 0) return;
    int pf = pos_h[t] * WW + pos_w[t];
    int idx = atomicAdd(&g_bincount[pf], 1);
    if (idx < MAXB) g_binlist[pf * MAXB + idx] = t;
}

// ---------------------------------------------------------------------------
// K2: per-bin Welford update + rstd. One 512-thread block per bin:
//     two 256-thread halves each sum alternate tokens (a = xbar - mean_old),
//     combine S1/S2 via smem, finalize in-block. Halves the per-bin critical
//     path (tail bins ~50 tokens) without a partials round-trip.
// ---------------------------------------------------------------------------
__global__ void __launch_bounds__(2 * P2) k_stats(const float* __restrict__ patches,
                                                  const float* __restrict__ n_in,
                                                  const float* __restrict__ mean_in,
                                                  const float* __restrict__ m2_in) {
    int bin  = blockIdx.x;
    int half = threadIdx.x >> 8;                 // 0 or 1
    int p    = threadIdx.x & (P2 - 1);           // 0..255

    __shared__ int   s_tok[MAXB];
    __shared__ int   s_cnt;
    __shared__ float s_s1[P2];
    __shared__ float s_s2[P2];

    if (threadIdx.x == 0) s_cnt = min(g_bincount[bin], MAXB);
    __syncthreads();
    int cnt = s_cnt;
    for (int i = threadIdx.x; i < cnt; i += 2 * P2) s_tok[i] = g_binlist[bin * MAXB + i];
    __syncthreads();

    float mo = mean_in[(size_t)bin * P2 + p];
    float s1 = 0.f, s2 = 0.f;
    const float c3 = 1.0f / 3.0f;

    // half h processes tokens h, h+2, h+4, ... ; unroll 4 -> 12 loads in flight
    int i = half;
    for (; i + 6 < cnt; i += 8) {
        const float* b0 = patches + (size_t)s_tok[i]     * DD;
        const float* b1 = patches + (size_t)s_tok[i + 2] * DD;
        const float* b2 = patches + (size_t)s_tok[i + 4] * DD;
        const float* b3 = patches + (size_t)s_tok[i + 6] * DD;
        float x00 = __ldcs(b0 + p), x01 = __ldcs(b0 + p + 256), x02 = __ldcs(b0 + p + 512);
        float x10 = __ldcs(b1 + p), x11 = __ldcs(b1 + p + 256), x12 = __ldcs(b1 + p + 512);
        float x20 = __ldcs(b2 + p), x21 = __ldcs(b2 + p + 256), x22 = __ldcs(b2 + p + 512);
        float x30 = __ldcs(b3 + p), x31 = __ldcs(b3 + p + 256), x32 = __ldcs(b3 + p + 512);
        float a0 = (x00 + x01 + x02) * c3 - mo;
        float a1 = (x10 + x11 + x12) * c3 - mo;
        float a2 = (x20 + x21 + x22) * c3 - mo;
        float a3 = (x30 + x31 + x32) * c3 - mo;
        s1 += a0; s2 += a0 * a0;
        s1 += a1; s2 += a1 * a1;
        s1 += a2; s2 += a2 * a2;
        s1 += a3; s2 += a3 * a3;
    }
    for (; i < cnt; i += 2) {
        const float* b0 = patches + (size_t)s_tok[i] * DD;
        float a0 = (__ldcs(b0 + p) + __ldcs(b0 + p + 256) + __ldcs(b0 + p + 512)) * c3 - mo;
        s1 += a0; s2 += a0 * a0;
    }

    // combine halves: half 1 publishes, half 0 finalizes
    if (half == 1) { s_s1[p] = s1; s_s2[p] = s2; }
    __syncthreads();
    if (half == 0) {
        s1 += s_s1[p];
        s2 += s_s2[p];

        float nn  = n_in[bin] + (float)cnt;
        float ng  = fmaxf(nn, 1.0f);
        float u   = s1 / ng;
        float mnv = mo + u;
        float m2v = m2_in[(size_t)bin * P2 + p] + (s2 - u * s1);
        float var = (nn < 2.0f) ? 1.0f : (m2v / ng);

        g_mnew[(size_t)bin * P2 + p] = mnv;
        g_rstd[(size_t)bin * P2 + p] = 1.0f / (sqrtf(var) + EPSV);
    }
}

// ---------------------------------------------------------------------------
// K3: normalize. 64 lanes per token; lane l owns stat column p = 4l and
//     processes all 3 channels -> stats gathered once, 5 loads in flight.
//     Streaming loads/stores keep L2 for the stat tables.
// ---------------------------------------------------------------------------
__global__ void __launch_bounds__(256) k_norm(const float* __restrict__ patches,
                                              const int* __restrict__ pos_h,
                                              const int* __restrict__ pos_w,
                                              const int* __restrict__ mask,
                                              float* __restrict__ out) {
    int t = blockIdx.x * 4 + (threadIdx.x >> 6);
    int lane = threadIdx.x & 63;

    const float4* xr   = (const float4*)(patches + (size_t)t * DD);
    float4*       orow = (float4*)(out + (size_t)t * DD);

    if (mask[t] != 0) {
        float4 z = make_float4(0.f, 0.f, 0.f, 0.f);
        __stcs(&orow[lane], z);
        __stcs(&orow[lane + 64], z);
        __stcs(&orow[lane + 128], z);
        return;
    }
    int pf = pos_h[t] * WW + pos_w[t];

    // issue all 5 loads before any consumer
    float4 x0 = __ldcs(&xr[lane]);
    float4 x1 = __ldcs(&xr[lane + 64]);
    float4 x2 = __ldcs(&xr[lane + 128]);
    float4 mn = ((const float4*)(g_mnew + (size_t)pf * P2))[lane];
    float4 rs = ((const float4*)(g_rstd + (size_t)pf * P2))[lane];

    float4 o0, o1, o2;
    o0.x = (x0.x - mn.x) * rs.x; o0.y = (x0.y - mn.y) * rs.y;
    o0.z = (x0.z - mn.z) * rs.z; o0.w = (x0.w - mn.w) * rs.w;
    o1.x = (x1.x - mn.x) * rs.x; o1.y = (x1.y - mn.y) * rs.y;
    o1.z = (x1.z - mn.z) * rs.z; o1.w = (x1.w - mn.w) * rs.w;
    o2.x = (x2.x - mn.x) * rs.x; o2.y = (x2.y - mn.y) * rs.y;
    o2.z = (x2.z - mn.z) * rs.z; o2.w = (x2.w - mn.w) * rs.w;

    __stcs(&orow[lane],       o0);
    __stcs(&orow[lane + 64],  o1);
    __stcs(&orow[lane + 128], o2);
}

// ---------------------------------------------------------------------------
extern "C" void kernel_launch(void* const* d_in, const int* in_sizes, int n_in,
                              void* d_out, int out_size) {
    const float* patches = (const float*)d_in[0];
    const int*   pos_h   = (const int*)d_in[1];
    const int*   pos_w   = (const int*)d_in[2];
    const int*   mask    = (const int*)d_in[3];    // bool widened to int32
    const float* n_in0   = (const float*)d_in[4];
    const float* mean_in = (const float*)d_in[5];
    const float* m2_in   = (const float*)d_in[6];
    float*       out     = (float*)d_out;

    k_zero <<<(HWB + 255) / 256, 256>>>();
    k_bin  <<<(NTOK + 255) / 256, 256>>>(pos_h, pos_w, mask);
    k_stats<<<HWB, 2 * P2>>>(patches, n_in0, mean_in, m2_in);
    k_norm <<<NTOK / 4, 256>>>(patches, pos_h, pos_w, mask, out);
}